// round 1
// baseline (speedup 1.0000x reference)
#include <cuda_runtime.h>
#include <math.h>

// Problem constants (from reference): B=2, T=8, N=65536, M=128, F=5, S=128
#define B_ 2
#define T_ 8
#define N_ 65536
#define M_ 128
#define F_ 5
#define S_ 128
#define GAMMA_ 1.1f

#define NTHREADS 256
#define NWARPS (NTHREADS / 32)

// One CTA per (b, t, m). Scan points in index order, select first <=128 inside
// the cylinder (xy distance <= radius), write them in order, zero-fill rest.
// Fallback: if t != 0 and valid_length[b,t,m] == 0, result equals the frame-0
// pool for (b, m) -> recompute using frame-0 points/rois (use_t = 0).
__global__ __launch_bounds__(NTHREADS)
void voxel_pool_kernel(const float* __restrict__ pts,
                       const float* __restrict__ rois,
                       const int* __restrict__ vl,
                       float* __restrict__ out)
{
    const int gid = blockIdx.x;             // (b*T + t)*M + m
    const int m = gid & (M_ - 1);
    const int t = (gid >> 7) & (T_ - 1);
    const int b = gid >> 10;
    const int tid  = threadIdx.x;
    const int lane = tid & 31;
    const int wid  = tid >> 5;

    int use_t = t;
    if (t != 0) {
        if (vl[(b * T_ + t) * M_ + m] == 0) use_t = 0;
    }

    __shared__ float s_cx, s_cy, s_thr;
    __shared__ int   s_cnt[NWARPS];

    if (tid == 0) {
        const float* roi = rois + ((size_t)(b * T_ + use_t) * M_ + m) * 7;
        const float cx = roi[0];
        const float cy = roi[1];
        // radii = ||[l,w]*0.5|| * GAMMA, replicated without FMA contraction
        const float hl = __fmul_rn(roi[3], 0.5f);
        const float hw = __fmul_rn(roi[4], 0.5f);
        const float r  = __fmul_rn(
            sqrtf(__fadd_rn(__fmul_rn(hl, hl), __fmul_rn(hw, hw))), GAMMA_);
        // thr = largest float x with sqrtf(x) <= r  (sqrtf is correctly
        // rounded + monotone, so (sqrtf(d2) <= r) <=> (d2 <= thr))
        float thr = __fmul_rn(r, r);
        while (sqrtf(thr) > r) {
            thr = __int_as_float(__float_as_int(thr) - 1);
        }
        for (;;) {
            float nxt = __int_as_float(__float_as_int(thr) + 1);
            if (sqrtf(nxt) <= r) thr = nxt; else break;
        }
        s_cx = cx; s_cy = cy; s_thr = thr;
    }
    __syncthreads();

    const float cx  = s_cx;
    const float cy  = s_cy;
    const float thr = s_thr;

    const float* P = pts + (size_t)(b * T_ + use_t) * N_ * F_;
    float* O = out + ((size_t)(b * M_ + m) * (T_ * S_) + (size_t)t * S_) * F_;

    int total = 0;  // identical across all threads (uniform control flow)
    for (int base = 0; base < N_; base += NTHREADS) {
        const int idx = base + tid;         // N_ is a multiple of NTHREADS
        const float x = P[idx * F_ + 0];
        const float y = P[idx * F_ + 1];
        const float dx = __fsub_rn(x, cx);
        const float dy = __fsub_rn(y, cy);
        const float d2 = __fadd_rn(__fmul_rn(dx, dx), __fmul_rn(dy, dy));
        const bool pred = (d2 <= thr);

        const unsigned bal = __ballot_sync(0xFFFFFFFFu, pred);
        if (lane == 0) s_cnt[wid] = __popc(bal);
        __syncthreads();

        int before = 0;
        int chunk_total = 0;
        #pragma unroll
        for (int w = 0; w < NWARPS; w++) {
            const int c = s_cnt[w];
            chunk_total += c;
            if (w < wid) before += c;
        }

        const int rank = total + before + __popc(bal & ((1u << lane) - 1u));
        if (pred && rank < S_) {
            const float* src = P + (size_t)idx * F_;
            float* dst = O + rank * F_;
            #pragma unroll
            for (int f = 0; f < F_; f++) dst[f] = src[f];
        }

        total += chunk_total;
        __syncthreads();  // protect s_cnt before next iteration's overwrite
        if (total >= S_) break;
    }

    // zero-fill rows [written, S)
    const int written = (total < S_) ? total : S_;
    const int zfl = (S_ - written) * F_;
    for (int i = tid; i < zfl; i += NTHREADS) {
        O[written * F_ + i] = 0.0f;
    }
}

extern "C" void kernel_launch(void* const* d_in, const int* in_sizes, int n_in,
                              void* d_out, int out_size)
{
    const float* pts  = (const float*)d_in[0];  // [B,T,N,F] f32
    const float* rois = (const float*)d_in[1];  // [B,T,M,7] f32
    const int*   vl   = (const int*)d_in[2];    // [B,T,M]   i32
    // d_in[3] = num_sample scalar, hardcoded to S_=128
    float* out = (float*)d_out;                 // [B,M,T*S,F] f32

    (void)in_sizes; (void)n_in; (void)out_size;
    voxel_pool_kernel<<<B_ * T_ * M_, NTHREADS>>>(pts, rois, vl, out);
}

// round 2
// speedup vs baseline: 1.1969x; 1.1969x over previous
#include <cuda_runtime.h>
#include <math.h>

// Problem constants: B=2, T=8, N=65536, M=128, F=5, S=128
#define B_ 2
#define T_ 8
#define N_ 65536
#define M_ 128
#define F_ 5
#define S_ 128
#define GAMMA_ 1.1f

#define NTHREADS 256
#define NWARPS (NTHREADS / 32)
#define PTS_PER_THREAD 8
#define CHUNK (NTHREADS * PTS_PER_THREAD)   // 2048
#define NCHUNKS (N_ / CHUNK)                // 32

// One CTA per (b, t, m). Scan points in index order, keep first <=128 inside
// the xy-cylinder, write in order, zero-fill the rest. Fallback for
// (t != 0 && valid_length==0): recompute with frame-0 points/rois.
__global__ __launch_bounds__(NTHREADS)
void voxel_pool_kernel(const float* __restrict__ pts,
                       const float* __restrict__ rois,
                       const int* __restrict__ vl,
                       float* __restrict__ out)
{
    const int gid = blockIdx.x;             // (b*T + t)*M + m
    const int m = gid & (M_ - 1);
    const int t = (gid >> 7) & (T_ - 1);
    const int b = gid >> 10;
    const int tid  = threadIdx.x;
    const int lane = tid & 31;
    const int wid  = tid >> 5;

    int use_t = t;
    if (t != 0 && vl[(b * T_ + t) * M_ + m] == 0) use_t = 0;

    __shared__ float s_cx, s_cy, s_thr;
    __shared__ int   s_cnt[2][NWARPS];

    if (tid == 0) {
        const float* roi = rois + ((size_t)(b * T_ + use_t) * M_ + m) * 7;
        const float cx = roi[0];
        const float cy = roi[1];
        const float hl = __fmul_rn(roi[3], 0.5f);
        const float hw = __fmul_rn(roi[4], 0.5f);
        const float r  = __fmul_rn(
            sqrtf(__fadd_rn(__fmul_rn(hl, hl), __fmul_rn(hw, hw))), GAMMA_);
        // Largest float x with sqrtf(x) <= r: makes (d2 <= thr) bit-identical
        // to (sqrtf(d2) <= r), eliminating the per-point sqrt.
        float thr = __fmul_rn(r, r);
        while (sqrtf(thr) > r) thr = __int_as_float(__float_as_int(thr) - 1);
        for (;;) {
            float nxt = __int_as_float(__float_as_int(thr) + 1);
            if (sqrtf(nxt) <= r) thr = nxt; else break;
        }
        s_cx = cx; s_cy = cy; s_thr = thr;
    }
    __syncthreads();

    const float cx  = s_cx;
    const float cy  = s_cy;
    const float thr = s_thr;

    const float*  P  = pts + (size_t)(b * T_ + use_t) * N_ * F_;
    const float4* P4 = (const float4*)P;
    float* O = out + ((size_t)(b * M_ + m) * (T_ * S_) + (size_t)t * S_) * F_;

    int total = 0;   // uniform across CTA
    int buf = 0;
    for (int chunk = 0; chunk < NCHUNKS; chunk++) {
        // This thread's 8 consecutive points = 40 floats = 10 float4 (16B-aligned).
        const int f4base = chunk * (CHUNK * F_ / 4) + tid * (PTS_PER_THREAD * F_ / 4);
        float4 q[10];
        #pragma unroll
        for (int i = 0; i < 10; i++) q[i] = P4[f4base + i];

        // Build 8-bit match mask (point j: x at flat float idx j*5, y at j*5+1).
        unsigned mask = 0;
        #pragma unroll
        for (int j = 0; j < PTS_PER_THREAD; j++) {
            const float* qf = (const float*)q;
            const float x = qf[j * 5 + 0];
            const float y = qf[j * 5 + 1];
            const float dx = __fsub_rn(x, cx);
            const float dy = __fsub_rn(y, cy);
            const float d2 = __fadd_rn(__fmul_rn(dx, dx), __fmul_rn(dy, dy));
            mask |= (d2 <= thr ? 1u : 0u) << j;
        }
        const int cnt = __popc(mask);

        // Warp inclusive scan of per-thread counts.
        int incl = cnt;
        #pragma unroll
        for (int d = 1; d < 32; d <<= 1) {
            const int v = __shfl_up_sync(0xFFFFFFFFu, incl, d);
            if (lane >= d) incl += v;
        }
        const int warpTotal = __shfl_sync(0xFFFFFFFFu, incl, 31);
        const int excl = incl - cnt;

        if (lane == 0) s_cnt[buf][wid] = warpTotal;
        __syncthreads();

        int before = 0, chunkTotal = 0;
        #pragma unroll
        for (int w = 0; w < NWARPS; w++) {
            const int c = s_cnt[buf][w];
            chunkTotal += c;
            if (w < wid) before += c;
        }

        // Ordered write of this thread's matches.
        int r = total + before + excl;
        #pragma unroll
        for (int j = 0; j < PTS_PER_THREAD; j++) {
            if ((mask >> j) & 1u) {
                if (r < S_) {
                    const float* qf = (const float*)q;
                    float* dst = O + r * F_;
                    #pragma unroll
                    for (int f = 0; f < F_; f++) dst[f] = qf[j * 5 + f];
                }
                r++;
            }
        }

        total += chunkTotal;
        buf ^= 1;
        if (total >= S_) break;   // uniform
    }

    // Zero-fill rows [written, S).
    const int written = (total < S_) ? total : S_;
    const int zfl = (S_ - written) * F_;
    for (int i = tid; i < zfl; i += NTHREADS) {
        O[written * F_ + i] = 0.0f;
    }
}

extern "C" void kernel_launch(void* const* d_in, const int* in_sizes, int n_in,
                              void* d_out, int out_size)
{
    const float* pts  = (const float*)d_in[0];  // [B,T,N,F] f32
    const float* rois = (const float*)d_in[1];  // [B,T,M,7] f32
    const int*   vl   = (const int*)d_in[2];    // [B,T,M]   i32
    float* out = (float*)d_out;                 // [B,M,T*S,F] f32

    (void)in_sizes; (void)n_in; (void)out_size;
    voxel_pool_kernel<<<B_ * T_ * M_, NTHREADS>>>(pts, rois, vl, out);
}

// round 3
// speedup vs baseline: 2.0360x; 1.7011x over previous
#include <cuda_runtime.h>
#include <math.h>

// Problem constants: B=2, T=8, N=65536, M=128, F=5, S=128
#define B_ 2
#define T_ 8
#define N_ 65536
#define M_ 128
#define F_ 5
#define S_ 128
#define GAMMA_ 1.1f

#define NTHREADS 256
#define NWARPS (NTHREADS / 32)
#define JGRP 4                      // point groups per thread
#define KIN 4                       // consecutive points per group (one float4)
#define CHUNK (NTHREADS * JGRP * KIN)   // 4096 points
#define NCHUNKS (N_ / CHUNK)            // 16
#define TOTALPTS (B_ * T_ * N_)         // 1,048,576

// SoA scratch for xy (predicate scan reads these coalesced).
__device__ float g_x[TOTALPTS];
__device__ float g_y[TOTALPTS];

__global__ __launch_bounds__(NTHREADS)
void transpose_xy_kernel(const float* __restrict__ pts)
{
    const int idx = blockIdx.x * NTHREADS + threadIdx.x;
    // TOTALPTS is a multiple of grid*block
    const float* p = pts + (size_t)idx * F_;
    g_x[idx] = p[0];
    g_y[idx] = p[1];
}

// One CTA per (b, t, m). Scan points in index order, keep first <=128 inside
// the xy-cylinder, write in order, zero-fill rest. Fallback for
// (t != 0 && valid_length==0): recompute with frame-0 points/rois.
__global__ __launch_bounds__(NTHREADS)
void voxel_pool_kernel(const float* __restrict__ pts,
                       const float* __restrict__ rois,
                       const int* __restrict__ vl,
                       float* __restrict__ out)
{
    const int gid = blockIdx.x;             // (b*T + t)*M + m
    const int m = gid & (M_ - 1);
    const int t = (gid >> 7) & (T_ - 1);
    const int b = gid >> 10;
    const int tid  = threadIdx.x;
    const int lane = tid & 31;
    const int wid  = tid >> 5;

    int use_t = t;
    if (t != 0 && vl[(b * T_ + t) * M_ + m] == 0) use_t = 0;

    __shared__ float s_cx, s_cy, s_thr;
    __shared__ unsigned s_cnt[2][NWARPS];

    if (tid == 0) {
        const float* roi = rois + ((size_t)(b * T_ + use_t) * M_ + m) * 7;
        const float cx = roi[0];
        const float cy = roi[1];
        const float hl = __fmul_rn(roi[3], 0.5f);
        const float hw = __fmul_rn(roi[4], 0.5f);
        const float r  = __fmul_rn(
            sqrtf(__fadd_rn(__fmul_rn(hl, hl), __fmul_rn(hw, hw))), GAMMA_);
        // Largest float x with sqrtf(x) <= r: (d2 <= thr) is bit-identical
        // to (sqrtf(d2) <= r); removes the per-point sqrt.
        float thr = __fmul_rn(r, r);
        while (sqrtf(thr) > r) thr = __int_as_float(__float_as_int(thr) - 1);
        for (;;) {
            float nxt = __int_as_float(__float_as_int(thr) + 1);
            if (sqrtf(nxt) <= r) thr = nxt; else break;
        }
        s_cx = cx; s_cy = cy; s_thr = thr;
    }
    __syncthreads();

    const float cx  = s_cx;
    const float cy  = s_cy;
    const float thr = s_thr;

    const int slab = b * T_ + use_t;
    const float*  P  = pts + (size_t)slab * N_ * F_;      // AoS, for gathers
    const float4* X4 = (const float4*)(g_x + (size_t)slab * N_);
    const float4* Y4 = (const float4*)(g_y + (size_t)slab * N_);
    float* O = out + ((size_t)(b * M_ + m) * (T_ * S_) + (size_t)t * S_) * F_;

    int total = 0;   // uniform across CTA
    int buf = 0;
    for (int chunk = 0; chunk < NCHUNKS; chunk++) {
        const int base4 = chunk * (CHUNK / 4);   // float4 index base
        // Thread owns points: chunk*4096 + j*1024 + tid*4 + k  (j<4, k<4).
        // For fixed j the warp's float4 loads are fully coalesced.
        float4 xa[JGRP], ya[JGRP];
        #pragma unroll
        for (int j = 0; j < JGRP; j++) {
            xa[j] = X4[base4 + j * NTHREADS + tid];
            ya[j] = Y4[base4 + j * NTHREADS + tid];
        }

        // 16-bit match mask, bit = j*4 + k.
        unsigned mask = 0;
        #pragma unroll
        for (int j = 0; j < JGRP; j++) {
            const float* xs = (const float*)&xa[j];
            const float* ys = (const float*)&ya[j];
            #pragma unroll
            for (int k = 0; k < KIN; k++) {
                const float dx = __fsub_rn(xs[k], cx);
                const float dy = __fsub_rn(ys[k], cy);
                const float d2 = __fadd_rn(__fmul_rn(dx, dx), __fmul_rn(dy, dy));
                mask |= (d2 <= thr ? 1u : 0u) << (j * KIN + k);
            }
        }

        // Byte-packed per-group counts: field j in byte j (<=4 per thread,
        // <=128 per warp -> no cross-byte carry in the packed scan).
        unsigned cp = 0;
        #pragma unroll
        for (int j = 0; j < JGRP; j++)
            cp |= (unsigned)__popc((mask >> (j * KIN)) & 0xFu) << (8 * j);

        unsigned incl = cp;
        #pragma unroll
        for (int d = 1; d < 32; d <<= 1) {
            const unsigned v = __shfl_up_sync(0xFFFFFFFFu, incl, d);
            if (lane >= d) incl += v;
        }
        const unsigned wtot = __shfl_sync(0xFFFFFFFFu, incl, 31);
        const unsigned excl = incl - cp;   // per-field, no borrow

        if (lane == 0) s_cnt[buf][wid] = wtot;
        __syncthreads();

        int fld_before[JGRP] = {0, 0, 0, 0};
        int fld_total[JGRP]  = {0, 0, 0, 0};
        #pragma unroll
        for (int w = 0; w < NWARPS; w++) {
            const unsigned v = s_cnt[buf][w];
            #pragma unroll
            for (int j = 0; j < JGRP; j++) {
                const int c = (int)((v >> (8 * j)) & 0xFFu);
                fld_total[j] += c;
                if (w < wid) fld_before[j] += c;
            }
        }
        const int chunkTotal =
            fld_total[0] + fld_total[1] + fld_total[2] + fld_total[3];

        // Ordered writes: rank = total + fields<j + warps<wid in j
        //                 + lanes<lane in j + bits<k.
        int fieldPrefix = 0;
        #pragma unroll
        for (int j = 0; j < JGRP; j++) {
            int r = total + fieldPrefix + fld_before[j]
                  + (int)((excl >> (8 * j)) & 0xFFu);
            const unsigned mj = (mask >> (j * KIN)) & 0xFu;
            #pragma unroll
            for (int k = 0; k < KIN; k++) {
                if ((mj >> k) & 1u) {
                    if (r < S_) {
                        const int ptidx =
                            chunk * CHUNK + j * (NTHREADS * KIN) + tid * KIN + k;
                        const float* src = P + (size_t)ptidx * F_;
                        float* dst = O + r * F_;
                        #pragma unroll
                        for (int f = 0; f < F_; f++) dst[f] = src[f];
                    }
                    r++;
                }
            }
            fieldPrefix += fld_total[j];
        }

        total += chunkTotal;
        buf ^= 1;
        if (total >= S_) break;   // uniform
    }

    // Zero-fill rows [written, S).
    const int written = (total < S_) ? total : S_;
    const int zfl = (S_ - written) * F_;
    for (int i = tid; i < zfl; i += NTHREADS) {
        O[written * F_ + i] = 0.0f;
    }
}

extern "C" void kernel_launch(void* const* d_in, const int* in_sizes, int n_in,
                              void* d_out, int out_size)
{
    const float* pts  = (const float*)d_in[0];  // [B,T,N,F] f32
    const float* rois = (const float*)d_in[1];  // [B,T,M,7] f32
    const int*   vl   = (const int*)d_in[2];    // [B,T,M]   i32
    float* out = (float*)d_out;                 // [B,M,T*S,F] f32

    (void)in_sizes; (void)n_in; (void)out_size;
    transpose_xy_kernel<<<TOTALPTS / NTHREADS, NTHREADS>>>(pts);
    voxel_pool_kernel<<<B_ * T_ * M_, NTHREADS>>>(pts, rois, vl, out);
}

// round 4
// speedup vs baseline: 2.5775x; 1.2660x over previous
#include <cuda_runtime.h>
#include <math.h>

// Problem constants: B=2, T=8, N=65536, M=128, F=5, S=128
#define B_ 2
#define T_ 8
#define N_ 65536
#define M_ 128
#define F_ 5
#define S_ 128
#define GAMMA_ 1.1f

#define NTHREADS 256
#define NWARPS 8
#define SUBPTS 4096                 // points per sub-chunk (16/thread)
#define TAILSC 3                    // sub-chunks per tail iteration
#define TOTALPTS (B_ * T_ * N_)     // 1,048,576

// SoA scratch for xy (predicate scan reads these coalesced).
__device__ __align__(16) float g_x[TOTALPTS];
__device__ __align__(16) float g_y[TOTALPTS];

// Vectorized AoS->SoA transpose: 4 points (= 5 float4) per thread.
__global__ __launch_bounds__(NTHREADS)
void transpose_xy_kernel(const float4* __restrict__ pts4)
{
    const int i4 = blockIdx.x * NTHREADS + threadIdx.x;  // group of 4 points
    const float4 p0 = pts4[i4 * 5 + 0];
    const float4 p1 = pts4[i4 * 5 + 1];
    const float4 p2 = pts4[i4 * 5 + 2];
    const float4 p3 = pts4[i4 * 5 + 3];
    const float4 p4 = pts4[i4 * 5 + 4];
    // flat floats f0..f19: x_j = f[5j], y_j = f[5j+1]
    ((float4*)g_x)[i4] = make_float4(p0.x, p1.y, p2.z, p3.w);
    ((float4*)g_y)[i4] = make_float4(p0.y, p1.z, p2.w, p4.x);
}

__device__ __forceinline__ unsigned long long spread4(unsigned v)
{
    return (unsigned long long)(v & 0xFFu)
         | ((unsigned long long)(v & 0xFF00u)     << 8)
         | ((unsigned long long)(v & 0xFF0000u)   << 16)
         | ((unsigned long long)(v & 0xFF000000u) << 24);
}

__device__ __forceinline__ unsigned predicate_mask(
    const float4* xv, const float4* yv, float cx, float cy, float thr)
{
    unsigned msk = 0;
    #pragma unroll
    for (int j = 0; j < 4; j++) {
        const float* xs = (const float*)&xv[j];
        const float* ys = (const float*)&yv[j];
        #pragma unroll
        for (int k = 0; k < 4; k++) {
            const float dx = __fsub_rn(xs[k], cx);
            const float dy = __fsub_rn(ys[k], cy);
            const float d2 = __fadd_rn(__fmul_rn(dx, dx), __fmul_rn(dy, dy));
            msk |= (d2 <= thr ? 1u : 0u) << (j * 4 + k);
        }
    }
    return msk;
}

__device__ __forceinline__ unsigned pack_counts(unsigned msk)
{
    unsigned cp = 0;
    #pragma unroll
    for (int j = 0; j < 4; j++)
        cp |= (unsigned)__popc((msk >> (4 * j)) & 0xFu) << (8 * j);
    return cp;
}

// Byte-packed inclusive warp scan; returns warp total, sets excl.
__device__ __forceinline__ unsigned packed_scan(unsigned cp, int lane, unsigned& excl)
{
    unsigned incl = cp;
    #pragma unroll
    for (int d = 1; d < 32; d <<= 1) {
        const unsigned v = __shfl_up_sync(0xFFFFFFFFu, incl, d);
        if (lane >= d) incl += v;
    }
    excl = incl - cp;
    return __shfl_sync(0xFFFFFFFFu, incl, 31);
}

// Unpack per-warp counts, write this thread's matches in order.
// Returns sub-chunk total (uniform).
__device__ __forceinline__ int write_subchunk(
    const unsigned long long* __restrict__ slot, int wid, int tid,
    unsigned mask, unsigned excl, int total, int ptbase,
    const float* __restrict__ P, float* __restrict__ O)
{
    unsigned long long tot64 = 0, bef64 = 0;
    #pragma unroll
    for (int w = 0; w < NWARPS; w++) {
        const unsigned long long v = slot[w];
        tot64 += v;
        if (w < wid) bef64 += v;
    }
    const unsigned a = (unsigned)tot64 + (unsigned)(tot64 >> 32);
    const int chunkTotal = (int)((a & 0xFFFFu) + (a >> 16));

    if (mask) {
        int fieldPrefix = 0;
        #pragma unroll
        for (int j = 0; j < 4; j++) {
            const int tj = (int)((tot64 >> (16 * j)) & 0xFFFFu);
            const int bj = (int)((bef64 >> (16 * j)) & 0xFFFFu);
            int r = total + fieldPrefix + bj + (int)((excl >> (8 * j)) & 0xFFu);
            unsigned mj = (mask >> (4 * j)) & 0xFu;
            while (mj) {
                const int k = __ffs(mj) - 1;
                mj &= mj - 1;
                if (r < S_) {
                    const int pt = ptbase + j * (NTHREADS * 4) + tid * 4 + k;
                    const float* src = P + (size_t)pt * F_;
                    float* dst = O + r * F_;
                    #pragma unroll
                    for (int f = 0; f < F_; f++) dst[f] = src[f];
                }
                r++;
            }
            fieldPrefix += tj;
        }
    }
    return chunkTotal;
}

// One CTA per (b, t, m). Keep first <=128 points inside the xy-cylinder in
// index order; zero-fill the rest. Fallback (t!=0 && valid_length==0):
// recompute with frame-0 points/rois.
__global__ __launch_bounds__(NTHREADS)
void voxel_pool_kernel(const float* __restrict__ pts,
                       const float* __restrict__ rois,
                       const int* __restrict__ vl,
                       float* __restrict__ out)
{
    const int gid = blockIdx.x;             // (b*T + t)*M + m
    const int m = gid & (M_ - 1);
    const int t = (gid >> 7) & (T_ - 1);
    const int b = gid >> 10;
    const int tid  = threadIdx.x;
    const int lane = tid & 31;
    const int wid  = tid >> 5;

    int use_t = t;
    if (t != 0 && vl[(b * T_ + t) * M_ + m] == 0) use_t = 0;

    const int slab = b * T_ + use_t;
    const float*  P  = pts + (size_t)slab * N_ * F_;
    const float4* X4 = (const float4*)(g_x + (size_t)slab * N_);
    const float4* Y4 = (const float4*)(g_y + (size_t)slab * N_);
    float* O = out + ((size_t)(b * M_ + m) * (T_ * S_) + (size_t)t * S_) * F_;

    __shared__ float s_cx, s_cy, s_thr;
    __shared__ unsigned long long s_cnt[2][TAILSC][NWARPS];

    // Chunk-0 loads issued BEFORE the setup barrier (don't depend on roi).
    float4 xv0[4], yv0[4];
    #pragma unroll
    for (int j = 0; j < 4; j++) {
        xv0[j] = X4[j * NTHREADS + tid];
        yv0[j] = Y4[j * NTHREADS + tid];
    }

    if (tid == 0) {
        const float* roi = rois + ((size_t)slab * M_ + m) * 7;
        const float cx = roi[0];
        const float cy = roi[1];
        const float hl = __fmul_rn(roi[3], 0.5f);
        const float hw = __fmul_rn(roi[4], 0.5f);
        const float r  = __fmul_rn(
            sqrtf(__fadd_rn(__fmul_rn(hl, hl), __fmul_rn(hw, hw))), GAMMA_);
        // Largest float x with sqrtf(x) <= r: (d2 <= thr) bit-identical to
        // (sqrtf(d2) <= r); removes the per-point sqrt.
        float thr = __fmul_rn(r, r);
        while (sqrtf(thr) > r) thr = __int_as_float(__float_as_int(thr) - 1);
        for (;;) {
            float nxt = __int_as_float(__float_as_int(thr) + 1);
            if (sqrtf(nxt) <= r) thr = nxt; else break;
        }
        s_cx = cx; s_cy = cy; s_thr = thr;
    }
    __syncthreads();

    const float cx  = s_cx;
    const float cy  = s_cy;
    const float thr = s_thr;

    // ---- Chunk 0 (4096 points) ----
    const unsigned mask0 = predicate_mask(xv0, yv0, cx, cy, thr);
    unsigned excl0;
    const unsigned wtot0 = packed_scan(pack_counts(mask0), lane, excl0);
    if (lane == 0) s_cnt[0][0][wid] = spread4(wtot0);
    __syncthreads();

    int total = write_subchunk(s_cnt[0][0], wid, tid, mask0, excl0, 0, 0, P, O);

    // ---- Tail: 5 iterations x 3 sub-chunks (12288 pts, one barrier each) ----
    for (int it = 0; it < 5 && total < S_; it++) {
        const int buf = (it & 1) ^ 1;
        const int ptbase = SUBPTS + it * (TAILSC * SUBPTS);

        unsigned masks[TAILSC], excls[TAILSC];
        #pragma unroll
        for (int sc = 0; sc < TAILSC; sc++) {
            const int off4 = (ptbase + sc * SUBPTS) / 4;
            float4 xv[4], yv[4];
            #pragma unroll
            for (int j = 0; j < 4; j++) {
                xv[j] = X4[off4 + j * NTHREADS + tid];
                yv[j] = Y4[off4 + j * NTHREADS + tid];
            }
            masks[sc] = predicate_mask(xv, yv, cx, cy, thr);
            const unsigned wt = packed_scan(pack_counts(masks[sc]), lane, excls[sc]);
            if (lane == 0) s_cnt[buf][sc][wid] = spread4(wt);
        }
        __syncthreads();

        #pragma unroll
        for (int sc = 0; sc < TAILSC; sc++) {
            if (total < S_) {
                total += write_subchunk(s_cnt[buf][sc], wid, tid,
                                        masks[sc], excls[sc], total,
                                        ptbase + sc * SUBPTS, P, O);
            }
        }
    }

    // Zero-fill rows [written, S).
    const int written = (total < S_) ? total : S_;
    const int zfl = (S_ - written) * F_;
    for (int i = tid; i < zfl; i += NTHREADS) {
        O[written * F_ + i] = 0.0f;
    }
}

extern "C" void kernel_launch(void* const* d_in, const int* in_sizes, int n_in,
                              void* d_out, int out_size)
{
    const float* pts  = (const float*)d_in[0];  // [B,T,N,F] f32
    const float* rois = (const float*)d_in[1];  // [B,T,M,7] f32
    const int*   vl   = (const int*)d_in[2];    // [B,T,M]   i32
    float* out = (float*)d_out;                 // [B,M,T*S,F] f32

    (void)in_sizes; (void)n_in; (void)out_size;
    transpose_xy_kernel<<<TOTALPTS / 4 / NTHREADS, NTHREADS>>>((const float4*)pts);
    voxel_pool_kernel<<<B_ * T_ * M_, NTHREADS>>>(pts, rois, vl, out);
}